// round 15
// baseline (speedup 1.0000x reference)
#include <cuda_runtime.h>
#include <stdint.h>

#define SRC_SIZE 262144
#define DST_SIZE 65536
#define N_EDGES  2097152
#define BATCH    4
#define FEAT     32

// Every dst segment padded to a multiple of 8 records (8-edge groups never
// straddle a segment). Max padded total = N_EDGES + 7*DST_SIZE = 2555904.
#define PAD_CAP   2556160                 // + slack for full-warp staging reads
#define N_GROUPS_CAP (PAD_CAP / 8)
#define GPW       16                      // 8-edge groups per warp (128 edges)
#define WPB_REDUCE 19968                  // warps per batch-pair = 2555904/128

#define SCAN_BLOCKS 256
#define SCAN_CHUNK  256   // DST_SIZE / SCAN_BLOCKS

#define FIX_SCALE 16777216.0f       // 2^24
#define INV_FIX   (1.0f / 16777216.0f)

// ---------------------------------------------------------------------------
// Scratch
// ---------------------------------------------------------------------------
__device__ unsigned long long g_hist[DST_SIZE];   // {count:u32 | fixed24(sum w):u32}
__device__ int            g_off[DST_SIZE];        // padded segment offset
__device__ float          g_inv[DST_SIZE];        // 1/(norm+1e-8)
__device__ unsigned short g_rank[N_EDGES];        // arrival rank within dst
__device__ int2           g_sorted[PAD_CAP];      // {src, __float_as_int(w)}
__device__ int            g_groupdst[N_GROUPS_CAP]; // dst id per 8-edge group
__device__ int            g_ngroups;              // actual number of groups

// ---------------------------------------------------------------------------
// K1: histogram (rank via returned count) + zero the output buffer.
// ---------------------------------------------------------------------------
__global__ void k_hist(const float* __restrict__ weights,
                       const int* __restrict__ dst_idx, int n_edges,
                       float4* __restrict__ out4, int n_out4) {
    int e = blockIdx.x * blockDim.x + threadIdx.x;
    if (e < n_edges) {
        int d = __ldg(&dst_idx[e]);
        float w = __ldg(&weights[e]);
        unsigned long long v =
            (1ULL << 32) | (unsigned long long)(unsigned int)(w * FIX_SCALE);
        unsigned long long old = atomicAdd(&g_hist[d], v);
        g_rank[e] = (unsigned short)(old >> 32);
    }
    if (e < n_out4)
        out4[e] = make_float4(0.f, 0.f, 0.f, 0.f);
}

// ---------------------------------------------------------------------------
// K2: merged scan over counts padded to multiples of 8. Emits g_off/g_inv,
// fills pad slots of g_sorted with {0,0} dummies, writes g_groupdst.
// ---------------------------------------------------------------------------
__global__ void k_scan() {
    __shared__ int sh[8];
    __shared__ int shp[8];
    __shared__ int s_prefix;

    const int t = threadIdx.x;
    const int lane = t & 31;
    const int warp = t >> 5;
    const int nprev = blockIdx.x * SCAN_CHUNK;

    int p0 = 0, p1 = 0, p2 = 0, p3 = 0;
    int i = t;
    for (; i + 768 < nprev; i += 1024) {
        p0 += ((int)(g_hist[i]       >> 32) + 7) & ~7;
        p1 += ((int)(g_hist[i + 256] >> 32) + 7) & ~7;
        p2 += ((int)(g_hist[i + 512] >> 32) + 7) & ~7;
        p3 += ((int)(g_hist[i + 768] >> 32) + 7) & ~7;
    }
    for (; i < nprev; i += 256) p0 += ((int)(g_hist[i] >> 32) + 7) & ~7;
    int p = (p0 + p1) + (p2 + p3);
#pragma unroll
    for (int off = 16; off > 0; off >>= 1)
        p += __shfl_down_sync(0xFFFFFFFFu, p, off);
    if (lane == 0) shp[warp] = p;
    __syncthreads();
    if (t == 0) {
        int acc = 0;
#pragma unroll
        for (int k = 0; k < 8; k++) acc += shp[k];
        s_prefix = acc;
    }

    const int d = nprev + t;
    unsigned long long h = g_hist[d];
    int c = (int)(h >> 32);
    int cp = (c + 7) & ~7;
    float norm = (float)(unsigned int)(h & 0xFFFFFFFFULL) * INV_FIX;

    int v = cp;
#pragma unroll
    for (int off = 1; off < 32; off <<= 1) {
        int n = __shfl_up_sync(0xFFFFFFFFu, v, off);
        if (lane >= off) v += n;
    }
    if (lane == 31) sh[warp] = v;
    __syncthreads();
    if (warp == 0) {
        int u = (lane < 8) ? sh[lane] : 0;
#pragma unroll
        for (int off = 1; off < 8; off <<= 1) {
            int n = __shfl_up_sync(0xFFFFFFFFu, u, off);
            if (lane >= off) u += n;
        }
        if (lane < 8) sh[lane] = u;
    }
    __syncthreads();
    int incl = v + ((warp > 0) ? sh[warp - 1] : 0);

    int off = s_prefix + incl - cp;
    g_off[d] = off;
    g_inv[d] = 1.0f / (norm + 1e-8f);

    // Fill pad slots with zero-weight dummies (gather row 0, contribute 0).
    for (int k = c; k < cp; k++)
        g_sorted[off + k] = make_int2(0, 0);

    // Group->dst map (off multiple of 8 => group-aligned).
    const int g0 = off >> 3, g1 = (off + cp) >> 3;
    for (int g = g0; g < g1; g++) g_groupdst[g] = d;

    if (d == DST_SIZE - 1) g_ngroups = (off + cp) >> 3;
}

// ---------------------------------------------------------------------------
// K3: atomic-free scatter: pos = g_off[dst] + rank[edge]
// ---------------------------------------------------------------------------
__global__ void k_scatter(const float* __restrict__ weights,
                          const int* __restrict__ src_idx,
                          const int* __restrict__ dst_idx, int n_edges) {
    int e = blockIdx.x * blockDim.x + threadIdx.x;
    if (e < n_edges) {
        int d = __ldg(&dst_idx[e]);
        int pos = __ldg(&g_off[d]) + (int)g_rank[e];
        int2 p;
        p.x = __ldg(&src_idx[e]);
        p.y = __float_as_int(__ldg(&weights[e]));
        g_sorted[pos] = p;
    }
}

// ---------------------------------------------------------------------------
// K4: FLAT edge-parallel reduction, ONE BATCH PAIR PER LAUNCH (perfect L2
// phase isolation: only this pair's 64MB x-slice is ever resident).
// Scalar-coalesced gathers, two batches per warp, GPW=16 groups (128 edges)
// per warp, full 16-gather ILP. Records + groupdst staged in smem.
// Lane = feature index (scalar LDG.32 = one coalesced 128B row = 1 L1 wf).
// Flush = one coalesced 32-lane atomicAdd per batch (out pre-zeroed).
// ---------------------------------------------------------------------------
__global__ void __launch_bounds__(128, 9)
k_reduce(const float* __restrict__ x, float* __restrict__ out, int bp) {
    __shared__ int4 s_rec[4][GPW * 4];   // per warp: 128 records = 64 int4 = 1KB
    __shared__ int  s_gd[4][GPW];        // per warp: 16 group-dst ids

    const int wid  = threadIdx.x >> 5;
    const int lane = threadIdx.x & 31;
    const int cnk  = blockIdx.x * 4 + wid;

    const int total = __ldg(&g_ngroups);
    const int g0 = cnk * GPW;
    if (g0 >= total) return;
    const int ng = (GPW < total - g0) ? GPW : (total - g0);

    // Stage records (64 int4 via 2 coalesced LDG.128) + groupdst (16 ints).
    {
        const int4* rsrc = (const int4*)&g_sorted[g0 << 3];
        s_rec[wid][lane]      = __ldcs(&rsrc[lane]);
        s_rec[wid][32 + lane] = __ldcs(&rsrc[32 + lane]);
        if (lane < GPW) {
            int gi = g0 + lane;
            s_gd[wid][lane] = (gi < total) ? __ldg(&g_groupdst[gi]) : 0;
        }
    }
    __syncwarp();

    const int b0 = bp * 2, b1 = bp * 2 + 1;
    const float* xb0 = x + (size_t)b0 * (SRC_SIZE * FEAT) + lane;
    const float* xb1 = x + (size_t)b1 * (SRC_SIZE * FEAT) + lane;
    float* o0 = out + (size_t)b0 * (DST_SIZE * FEAT) + lane;
    float* o1 = out + (size_t)b1 * (DST_SIZE * FEAT) + lane;

    int d_cur = s_gd[wid][0];
    float p0 = 0.f, p1 = 0.f;   // batch b0 accumulators
    float q0 = 0.f, q1 = 0.f;   // batch b1 accumulators

    for (int i = 0; i < ng; i++) {
        int gd = s_gd[wid][i];
        int4 r0 = s_rec[wid][i * 4 + 0];
        int4 r1 = s_rec[wid][i * 4 + 1];
        int4 r2 = s_rec[wid][i * 4 + 2];
        int4 r3 = s_rec[wid][i * 4 + 3];
        // 16 coalesced scalar gathers (8 per batch) in flight.
        float u0 = __ldg(xb0 + (size_t)r0.x * FEAT);
        float u1 = __ldg(xb0 + (size_t)r0.z * FEAT);
        float u2 = __ldg(xb0 + (size_t)r1.x * FEAT);
        float u3 = __ldg(xb0 + (size_t)r1.z * FEAT);
        float u4 = __ldg(xb0 + (size_t)r2.x * FEAT);
        float u5 = __ldg(xb0 + (size_t)r2.z * FEAT);
        float u6 = __ldg(xb0 + (size_t)r3.x * FEAT);
        float u7 = __ldg(xb0 + (size_t)r3.z * FEAT);
        float t0 = __ldg(xb1 + (size_t)r0.x * FEAT);
        float t1 = __ldg(xb1 + (size_t)r0.z * FEAT);
        float t2 = __ldg(xb1 + (size_t)r1.x * FEAT);
        float t3 = __ldg(xb1 + (size_t)r1.z * FEAT);
        float t4 = __ldg(xb1 + (size_t)r2.x * FEAT);
        float t5 = __ldg(xb1 + (size_t)r2.z * FEAT);
        float t6 = __ldg(xb1 + (size_t)r3.x * FEAT);
        float t7 = __ldg(xb1 + (size_t)r3.z * FEAT);
        if (gd != d_cur) {
            float inv = __ldg(&g_inv[d_cur]);
            atomicAdd(o0 + (size_t)d_cur * FEAT, (p0 + p1) * inv);
            atomicAdd(o1 + (size_t)d_cur * FEAT, (q0 + q1) * inv);
            p0 = p1 = q0 = q1 = 0.f;
            d_cur = gd;
        }
        float w0 = __int_as_float(r0.y), w1 = __int_as_float(r0.w);
        float w2 = __int_as_float(r1.y), w3 = __int_as_float(r1.w);
        float w4 = __int_as_float(r2.y), w5 = __int_as_float(r2.w);
        float w6 = __int_as_float(r3.y), w7 = __int_as_float(r3.w);
        p0 += w0 * u0;  p1 += w1 * u1;
        p0 += w2 * u2;  p1 += w3 * u3;
        p0 += w4 * u4;  p1 += w5 * u5;
        p0 += w6 * u6;  p1 += w7 * u7;
        q0 += w0 * t0;  q1 += w1 * t1;
        q0 += w2 * t2;  q1 += w3 * t3;
        q0 += w4 * t4;  q1 += w5 * t5;
        q0 += w6 * t6;  q1 += w7 * t7;
    }
    {
        float inv = __ldg(&g_inv[d_cur]);
        atomicAdd(o0 + (size_t)d_cur * FEAT, (p0 + p1) * inv);
        atomicAdd(o1 + (size_t)d_cur * FEAT, (q0 + q1) * inv);
    }
}

// ---------------------------------------------------------------------------
// kernel_launch
// ---------------------------------------------------------------------------
extern "C" void kernel_launch(void* const* d_in, const int* in_sizes, int n_in,
                              void* d_out, int out_size) {
    const float* x       = (const float*)d_in[0];
    const float* weights = (const float*)d_in[1];
    const int*   src_idx = (const int*)d_in[2];
    const int*   dst_idx = (const int*)d_in[3];
    float*       out     = (float*)d_out;
    const int n_edges = in_sizes[1];
    const int n_out4  = out_size / 4;

    void* hist_ptr = nullptr;
    cudaGetSymbolAddress(&hist_ptr, g_hist);
    cudaMemsetAsync(hist_ptr, 0, DST_SIZE * sizeof(unsigned long long), 0);

    k_hist<<<(n_edges + 255) / 256, 256>>>(weights, dst_idx, n_edges,
                                           (float4*)out, n_out4);
    k_scan<<<SCAN_BLOCKS, SCAN_CHUNK>>>();
    k_scatter<<<(n_edges + 255) / 256, 256>>>(weights, src_idx, dst_idx, n_edges);
    // One launch per batch pair: perfect L2 phase isolation.
    k_reduce<<<WPB_REDUCE / 4, 128>>>(x, out, 0);
    k_reduce<<<WPB_REDUCE / 4, 128>>>(x, out, 1);
}

// round 16
// speedup vs baseline: 1.0478x; 1.0478x over previous
#include <cuda_runtime.h>
#include <stdint.h>

#define SRC_SIZE 262144
#define DST_SIZE 65536
#define N_EDGES  2097152
#define BATCH    4
#define FEAT     32

// Every dst segment padded to a multiple of 8 records (8-edge groups never
// straddle a segment). Max padded total = N_EDGES + 7*DST_SIZE = 2555904.
#define PAD_CAP   2556160                 // + slack for full-warp staging reads
#define N_GROUPS_CAP (PAD_CAP / 8)
#define GPW       16                      // 8-edge groups per warp (128 edges)
#define WPB_REDUCE 19968                  // warps per batch-pair = 2555904/128

#define SCAN_BLOCKS 256
#define SCAN_CHUNK  256   // DST_SIZE / SCAN_BLOCKS

#define FIX_SCALE 16777216.0f       // 2^24
#define INV_FIX   (1.0f / 16777216.0f)

// ---------------------------------------------------------------------------
// Scratch
// ---------------------------------------------------------------------------
__device__ unsigned long long g_hist[DST_SIZE];   // {count:u32 | fixed24(sum w):u32}
__device__ int            g_off[DST_SIZE];        // padded segment offset
__device__ float          g_inv[DST_SIZE];        // 1/(norm+1e-8)
__device__ unsigned short g_rank[N_EDGES];        // arrival rank within dst
__device__ int2           g_sorted[PAD_CAP];      // {src, __float_as_int(w)}
__device__ int            g_groupdst[N_GROUPS_CAP]; // dst id per 8-edge group
__device__ int            g_ngroups;              // actual number of groups

// ---------------------------------------------------------------------------
// K1: histogram (rank via returned count) + zero the output buffer.
// ---------------------------------------------------------------------------
__global__ void k_hist(const float* __restrict__ weights,
                       const int* __restrict__ dst_idx, int n_edges,
                       float4* __restrict__ out4, int n_out4) {
    int e = blockIdx.x * blockDim.x + threadIdx.x;
    if (e < n_edges) {
        int d = __ldg(&dst_idx[e]);
        float w = __ldg(&weights[e]);
        unsigned long long v =
            (1ULL << 32) | (unsigned long long)(unsigned int)(w * FIX_SCALE);
        unsigned long long old = atomicAdd(&g_hist[d], v);
        g_rank[e] = (unsigned short)(old >> 32);
    }
    if (e < n_out4)
        out4[e] = make_float4(0.f, 0.f, 0.f, 0.f);
}

// ---------------------------------------------------------------------------
// K2: merged scan over counts padded to multiples of 8. Emits g_off/g_inv,
// fills pad slots of g_sorted with {0,0} dummies, writes g_groupdst.
// ---------------------------------------------------------------------------
__global__ void k_scan() {
    __shared__ int sh[8];
    __shared__ int shp[8];
    __shared__ int s_prefix;

    const int t = threadIdx.x;
    const int lane = t & 31;
    const int warp = t >> 5;
    const int nprev = blockIdx.x * SCAN_CHUNK;

    int p0 = 0, p1 = 0, p2 = 0, p3 = 0;
    int i = t;
    for (; i + 768 < nprev; i += 1024) {
        p0 += ((int)(g_hist[i]       >> 32) + 7) & ~7;
        p1 += ((int)(g_hist[i + 256] >> 32) + 7) & ~7;
        p2 += ((int)(g_hist[i + 512] >> 32) + 7) & ~7;
        p3 += ((int)(g_hist[i + 768] >> 32) + 7) & ~7;
    }
    for (; i < nprev; i += 256) p0 += ((int)(g_hist[i] >> 32) + 7) & ~7;
    int p = (p0 + p1) + (p2 + p3);
#pragma unroll
    for (int off = 16; off > 0; off >>= 1)
        p += __shfl_down_sync(0xFFFFFFFFu, p, off);
    if (lane == 0) shp[warp] = p;
    __syncthreads();
    if (t == 0) {
        int acc = 0;
#pragma unroll
        for (int k = 0; k < 8; k++) acc += shp[k];
        s_prefix = acc;
    }

    const int d = nprev + t;
    unsigned long long h = g_hist[d];
    int c = (int)(h >> 32);
    int cp = (c + 7) & ~7;
    float norm = (float)(unsigned int)(h & 0xFFFFFFFFULL) * INV_FIX;

    int v = cp;
#pragma unroll
    for (int off = 1; off < 32; off <<= 1) {
        int n = __shfl_up_sync(0xFFFFFFFFu, v, off);
        if (lane >= off) v += n;
    }
    if (lane == 31) sh[warp] = v;
    __syncthreads();
    if (warp == 0) {
        int u = (lane < 8) ? sh[lane] : 0;
#pragma unroll
        for (int off = 1; off < 8; off <<= 1) {
            int n = __shfl_up_sync(0xFFFFFFFFu, u, off);
            if (lane >= off) u += n;
        }
        if (lane < 8) sh[lane] = u;
    }
    __syncthreads();
    int incl = v + ((warp > 0) ? sh[warp - 1] : 0);

    int off = s_prefix + incl - cp;
    g_off[d] = off;
    g_inv[d] = 1.0f / (norm + 1e-8f);

    // Fill pad slots with zero-weight dummies (gather row 0, contribute 0).
    for (int k = c; k < cp; k++)
        g_sorted[off + k] = make_int2(0, 0);

    // Group->dst map (off multiple of 8 => group-aligned).
    const int g0 = off >> 3, g1 = (off + cp) >> 3;
    for (int g = g0; g < g1; g++) g_groupdst[g] = d;

    if (d == DST_SIZE - 1) g_ngroups = (off + cp) >> 3;
}

// ---------------------------------------------------------------------------
// K3: atomic-free scatter: pos = g_off[dst] + rank[edge]. Streaming store.
// ---------------------------------------------------------------------------
__global__ void k_scatter(const float* __restrict__ weights,
                          const int* __restrict__ src_idx,
                          const int* __restrict__ dst_idx, int n_edges) {
    int e = blockIdx.x * blockDim.x + threadIdx.x;
    if (e < n_edges) {
        int d = __ldg(&dst_idx[e]);
        int pos = __ldg(&g_off[d]) + (int)g_rank[e];
        int2 p;
        p.x = __ldg(&src_idx[e]);
        p.y = __float_as_int(__ldg(&weights[e]));
        __stcg(&g_sorted[pos], p);
    }
}

// ---------------------------------------------------------------------------
// K4: FLAT edge-parallel reduction (R14 single-launch structure).
// Scalar-coalesced gathers, TWO BATCHES per warp, GPW=16 groups (128 edges)
// per warp, full 16-gather ILP. Records + groupdst staged in smem.
// Lane = feature index (scalar LDG.32 = one coalesced 128B row = 1 L1 wf).
// Flush = one coalesced 32-lane atomicAdd per batch (out pre-zeroed).
// Warps pair-major so one 64MB x-slice pair is hot in L2 at a time.
// ---------------------------------------------------------------------------
__global__ void __launch_bounds__(128, 9)
k_reduce(const float* __restrict__ x, float* __restrict__ out) {
    __shared__ int4 s_rec[4][GPW * 4];   // per warp: 128 records = 64 int4 = 1KB
    __shared__ int  s_gd[4][GPW];        // per warp: 16 group-dst ids

    const int wid  = threadIdx.x >> 5;
    const int lane = threadIdx.x & 31;
    const int wg   = blockIdx.x * 4 + wid;
    const int bp   = wg / WPB_REDUCE;          // batch pair 0 -> {0,1}, 1 -> {2,3}
    const int cnk  = wg - bp * WPB_REDUCE;

    const int total = __ldg(&g_ngroups);
    const int g0 = cnk * GPW;
    if (g0 >= total) return;
    const int ng = (GPW < total - g0) ? GPW : (total - g0);

    // Stage records (64 int4 via 2 coalesced LDG.128) + groupdst (16 ints).
    {
        const int4* rsrc = (const int4*)&g_sorted[g0 << 3];
        s_rec[wid][lane]      = __ldcs(&rsrc[lane]);
        s_rec[wid][32 + lane] = __ldcs(&rsrc[32 + lane]);
        if (lane < GPW) {
            int gi = g0 + lane;
            s_gd[wid][lane] = (gi < total) ? __ldg(&g_groupdst[gi]) : 0;
        }
    }
    __syncwarp();

    const int b0 = bp * 2, b1 = bp * 2 + 1;
    const float* xb0 = x + (size_t)b0 * (SRC_SIZE * FEAT) + lane;
    const float* xb1 = x + (size_t)b1 * (SRC_SIZE * FEAT) + lane;
    float* o0 = out + (size_t)b0 * (DST_SIZE * FEAT) + lane;
    float* o1 = out + (size_t)b1 * (DST_SIZE * FEAT) + lane;

    int d_cur = s_gd[wid][0];
    float p0 = 0.f, p1 = 0.f;   // batch b0 accumulators
    float q0 = 0.f, q1 = 0.f;   // batch b1 accumulators

    for (int i = 0; i < ng; i++) {
        int gd = s_gd[wid][i];
        int4 r0 = s_rec[wid][i * 4 + 0];
        int4 r1 = s_rec[wid][i * 4 + 1];
        int4 r2 = s_rec[wid][i * 4 + 2];
        int4 r3 = s_rec[wid][i * 4 + 3];
        // 16 coalesced scalar gathers (8 per batch) in flight.
        float u0 = __ldg(xb0 + (size_t)r0.x * FEAT);
        float u1 = __ldg(xb0 + (size_t)r0.z * FEAT);
        float u2 = __ldg(xb0 + (size_t)r1.x * FEAT);
        float u3 = __ldg(xb0 + (size_t)r1.z * FEAT);
        float u4 = __ldg(xb0 + (size_t)r2.x * FEAT);
        float u5 = __ldg(xb0 + (size_t)r2.z * FEAT);
        float u6 = __ldg(xb0 + (size_t)r3.x * FEAT);
        float u7 = __ldg(xb0 + (size_t)r3.z * FEAT);
        float t0 = __ldg(xb1 + (size_t)r0.x * FEAT);
        float t1 = __ldg(xb1 + (size_t)r0.z * FEAT);
        float t2 = __ldg(xb1 + (size_t)r1.x * FEAT);
        float t3 = __ldg(xb1 + (size_t)r1.z * FEAT);
        float t4 = __ldg(xb1 + (size_t)r2.x * FEAT);
        float t5 = __ldg(xb1 + (size_t)r2.z * FEAT);
        float t6 = __ldg(xb1 + (size_t)r3.x * FEAT);
        float t7 = __ldg(xb1 + (size_t)r3.z * FEAT);
        if (gd != d_cur) {
            float inv = __ldg(&g_inv[d_cur]);
            atomicAdd(o0 + (size_t)d_cur * FEAT, (p0 + p1) * inv);
            atomicAdd(o1 + (size_t)d_cur * FEAT, (q0 + q1) * inv);
            p0 = p1 = q0 = q1 = 0.f;
            d_cur = gd;
        }
        float w0 = __int_as_float(r0.y), w1 = __int_as_float(r0.w);
        float w2 = __int_as_float(r1.y), w3 = __int_as_float(r1.w);
        float w4 = __int_as_float(r2.y), w5 = __int_as_float(r2.w);
        float w6 = __int_as_float(r3.y), w7 = __int_as_float(r3.w);
        p0 += w0 * u0;  p1 += w1 * u1;
        p0 += w2 * u2;  p1 += w3 * u3;
        p0 += w4 * u4;  p1 += w5 * u5;
        p0 += w6 * u6;  p1 += w7 * u7;
        q0 += w0 * t0;  q1 += w1 * t1;
        q0 += w2 * t2;  q1 += w3 * t3;
        q0 += w4 * t4;  q1 += w5 * t5;
        q0 += w6 * t6;  q1 += w7 * t7;
    }
    {
        float inv = __ldg(&g_inv[d_cur]);
        atomicAdd(o0 + (size_t)d_cur * FEAT, (p0 + p1) * inv);
        atomicAdd(o1 + (size_t)d_cur * FEAT, (q0 + q1) * inv);
    }
}

// ---------------------------------------------------------------------------
// kernel_launch
// ---------------------------------------------------------------------------
extern "C" void kernel_launch(void* const* d_in, const int* in_sizes, int n_in,
                              void* d_out, int out_size) {
    const float* x       = (const float*)d_in[0];
    const float* weights = (const float*)d_in[1];
    const int*   src_idx = (const int*)d_in[2];
    const int*   dst_idx = (const int*)d_in[3];
    float*       out     = (float*)d_out;
    const int n_edges = in_sizes[1];
    const int n_out4  = out_size / 4;

    void* hist_ptr = nullptr;
    cudaGetSymbolAddress(&hist_ptr, g_hist);
    cudaMemsetAsync(hist_ptr, 0, DST_SIZE * sizeof(unsigned long long), 0);

    k_hist<<<(n_edges + 255) / 256, 256>>>(weights, dst_idx, n_edges,
                                           (float4*)out, n_out4);
    k_scan<<<SCAN_BLOCKS, SCAN_CHUNK>>>();
    k_scatter<<<(n_edges + 255) / 256, 256>>>(weights, src_idx, dst_idx, n_edges);
    // 2 batch-pairs * WPB_REDUCE warps, 4 warps/block, pair-major, ONE launch.
    k_reduce<<<(2 * WPB_REDUCE) / 4, 128>>>(x, out);
}

// round 17
// speedup vs baseline: 1.0570x; 1.0087x over previous
#include <cuda_runtime.h>
#include <stdint.h>

#define SRC_SIZE 262144
#define DST_SIZE 65536
#define N_EDGES  2097152
#define BATCH    4
#define FEAT     32

// Every dst segment padded to a multiple of 8 records (8-edge groups never
// straddle a segment). Max padded total = N_EDGES + 7*DST_SIZE = 2555904.
#define PAD_CAP   2556160                 // + slack for full-warp staging reads
#define N_GROUPS_CAP (PAD_CAP / 8)
#define GPW       16                      // 8-edge groups per warp (128 edges)
#define WPB_REDUCE 19968                  // warps per batch-pair = 2555904/128

#define SCAN_BLOCKS 256
#define SCAN_CHUNK  256   // DST_SIZE / SCAN_BLOCKS

#define FIX_SCALE 16777216.0f       // 2^24
#define INV_FIX   (1.0f / 16777216.0f)

// ---------------------------------------------------------------------------
// Scratch
// ---------------------------------------------------------------------------
__device__ unsigned long long g_hist[DST_SIZE];   // {count:u32 | fixed24(sum w):u32}
__device__ int            g_off[DST_SIZE];        // padded segment offset
__device__ float          g_inv[DST_SIZE];        // 1/(norm+1e-8)
__device__ unsigned short g_rank[N_EDGES];        // arrival rank within dst
__device__ int2           g_sorted[PAD_CAP];      // {src, __float_as_int(w)}
__device__ int            g_groupdst[N_GROUPS_CAP]; // dst id per 8-edge group
__device__ int            g_ngroups;              // actual number of groups

// ---------------------------------------------------------------------------
// K1: histogram (rank via returned count) + zero the output buffer.
// ---------------------------------------------------------------------------
__global__ void k_hist(const float* __restrict__ weights,
                       const int* __restrict__ dst_idx, int n_edges,
                       float4* __restrict__ out4, int n_out4) {
    int e = blockIdx.x * blockDim.x + threadIdx.x;
    if (e < n_edges) {
        int d = __ldg(&dst_idx[e]);
        float w = __ldg(&weights[e]);
        unsigned long long v =
            (1ULL << 32) | (unsigned long long)(unsigned int)(w * FIX_SCALE);
        unsigned long long old = atomicAdd(&g_hist[d], v);
        g_rank[e] = (unsigned short)(old >> 32);
    }
    if (e < n_out4)
        out4[e] = make_float4(0.f, 0.f, 0.f, 0.f);
}

// ---------------------------------------------------------------------------
// K2: merged scan over counts padded to multiples of 8. Emits g_off/g_inv,
// fills pad slots of g_sorted with {0,0} dummies, writes g_groupdst.
// ---------------------------------------------------------------------------
__global__ void k_scan() {
    __shared__ int sh[8];
    __shared__ int shp[8];
    __shared__ int s_prefix;

    const int t = threadIdx.x;
    const int lane = t & 31;
    const int warp = t >> 5;
    const int nprev = blockIdx.x * SCAN_CHUNK;

    int p0 = 0, p1 = 0, p2 = 0, p3 = 0;
    int i = t;
    for (; i + 768 < nprev; i += 1024) {
        p0 += ((int)(g_hist[i]       >> 32) + 7) & ~7;
        p1 += ((int)(g_hist[i + 256] >> 32) + 7) & ~7;
        p2 += ((int)(g_hist[i + 512] >> 32) + 7) & ~7;
        p3 += ((int)(g_hist[i + 768] >> 32) + 7) & ~7;
    }
    for (; i < nprev; i += 256) p0 += ((int)(g_hist[i] >> 32) + 7) & ~7;
    int p = (p0 + p1) + (p2 + p3);
#pragma unroll
    for (int off = 16; off > 0; off >>= 1)
        p += __shfl_down_sync(0xFFFFFFFFu, p, off);
    if (lane == 0) shp[warp] = p;
    __syncthreads();
    if (t == 0) {
        int acc = 0;
#pragma unroll
        for (int k = 0; k < 8; k++) acc += shp[k];
        s_prefix = acc;
    }

    const int d = nprev + t;
    unsigned long long h = g_hist[d];
    int c = (int)(h >> 32);
    int cp = (c + 7) & ~7;
    float norm = (float)(unsigned int)(h & 0xFFFFFFFFULL) * INV_FIX;

    int v = cp;
#pragma unroll
    for (int off = 1; off < 32; off <<= 1) {
        int n = __shfl_up_sync(0xFFFFFFFFu, v, off);
        if (lane >= off) v += n;
    }
    if (lane == 31) sh[warp] = v;
    __syncthreads();
    if (warp == 0) {
        int u = (lane < 8) ? sh[lane] : 0;
#pragma unroll
        for (int off = 1; off < 8; off <<= 1) {
            int n = __shfl_up_sync(0xFFFFFFFFu, u, off);
            if (lane >= off) u += n;
        }
        if (lane < 8) sh[lane] = u;
    }
    __syncthreads();
    int incl = v + ((warp > 0) ? sh[warp - 1] : 0);

    int off = s_prefix + incl - cp;
    g_off[d] = off;
    g_inv[d] = 1.0f / (norm + 1e-8f);

    // Fill pad slots with zero-weight dummies (gather row 0, contribute 0).
    for (int k = c; k < cp; k++)
        g_sorted[off + k] = make_int2(0, 0);

    // Group->dst map (off multiple of 8 => group-aligned).
    const int g0 = off >> 3, g1 = (off + cp) >> 3;
    for (int g = g0; g < g1; g++) g_groupdst[g] = d;

    if (d == DST_SIZE - 1) g_ngroups = (off + cp) >> 3;
}

// ---------------------------------------------------------------------------
// K3: atomic-free scatter: pos = g_off[dst] + rank[edge]. Streaming store.
// ---------------------------------------------------------------------------
__global__ void k_scatter(const float* __restrict__ weights,
                          const int* __restrict__ src_idx,
                          const int* __restrict__ dst_idx, int n_edges) {
    int e = blockIdx.x * blockDim.x + threadIdx.x;
    if (e < n_edges) {
        int d = __ldg(&dst_idx[e]);
        int pos = __ldg(&g_off[d]) + (int)g_rank[e];
        int2 p;
        p.x = __ldg(&src_idx[e]);
        p.y = __float_as_int(__ldg(&weights[e]));
        __stcg(&g_sorted[pos], p);
    }
}

// ---------------------------------------------------------------------------
// K4: FLAT edge-parallel reduction (R14 structure) with 32-BIT GATHER
// ADDRESSING (src*FEAT*4 <= 33MB fits u32 -> no 64-bit IMAD chains, lower
// register pressure) and __launch_bounds__(128, 10) for 40 warps/SM.
// Scalar-coalesced gathers, TWO BATCHES per warp, GPW=16 groups (128 edges),
// full 16-gather ILP. Records + groupdst staged in smem. Lane = feature
// index. Flush = one coalesced 32-lane atomicAdd per batch (out pre-zeroed).
// Warps pair-major so one 64MB x-slice pair is hot in L2 at a time.
// ---------------------------------------------------------------------------
__global__ void __launch_bounds__(128, 10)
k_reduce(const float* __restrict__ x, float* __restrict__ out) {
    __shared__ int4 s_rec[4][GPW * 4];   // per warp: 128 records = 64 int4 = 1KB
    __shared__ int  s_gd[4][GPW];        // per warp: 16 group-dst ids

    const int wid  = threadIdx.x >> 5;
    const int lane = threadIdx.x & 31;
    const int wg   = blockIdx.x * 4 + wid;
    const int bp   = wg / WPB_REDUCE;          // batch pair 0 -> {0,1}, 1 -> {2,3}
    const int cnk  = wg - bp * WPB_REDUCE;

    const int total = __ldg(&g_ngroups);
    const int g0 = cnk * GPW;
    if (g0 >= total) return;
    const int ng = (GPW < total - g0) ? GPW : (total - g0);

    // Stage records (64 int4 via 2 coalesced LDG.128) + groupdst (16 ints).
    {
        const int4* rsrc = (const int4*)&g_sorted[g0 << 3];
        s_rec[wid][lane]      = __ldcs(&rsrc[lane]);
        s_rec[wid][32 + lane] = __ldcs(&rsrc[32 + lane]);
        if (lane < GPW) {
            int gi = g0 + lane;
            s_gd[wid][lane] = (gi < total) ? __ldg(&g_groupdst[gi]) : 0;
        }
    }
    __syncwarp();

    const int b0 = bp * 2, b1 = bp * 2 + 1;
    const float* xb0 = x + (size_t)b0 * (SRC_SIZE * FEAT) + lane;
    const float* xb1 = x + (size_t)b1 * (SRC_SIZE * FEAT) + lane;
    float* o0 = out + (size_t)b0 * (DST_SIZE * FEAT) + lane;
    float* o1 = out + (size_t)b1 * (DST_SIZE * FEAT) + lane;

    int d_cur = s_gd[wid][0];
    float p0 = 0.f, p1 = 0.f;   // batch b0 accumulators
    float q0 = 0.f, q1 = 0.f;   // batch b1 accumulators

    for (int i = 0; i < ng; i++) {
        int gd = s_gd[wid][i];
        int4 r0 = s_rec[wid][i * 4 + 0];
        int4 r1 = s_rec[wid][i * 4 + 1];
        int4 r2 = s_rec[wid][i * 4 + 2];
        int4 r3 = s_rec[wid][i * 4 + 3];
        // 32-bit row offsets (src << 5 floats).
        unsigned c0 = (unsigned)r0.x << 5, c1 = (unsigned)r0.z << 5;
        unsigned c2 = (unsigned)r1.x << 5, c3 = (unsigned)r1.z << 5;
        unsigned c4 = (unsigned)r2.x << 5, c5 = (unsigned)r2.z << 5;
        unsigned c6 = (unsigned)r3.x << 5, c7 = (unsigned)r3.z << 5;
        // 16 coalesced scalar gathers (8 per batch) in flight.
        float u0 = __ldg(xb0 + c0);
        float u1 = __ldg(xb0 + c1);
        float u2 = __ldg(xb0 + c2);
        float u3 = __ldg(xb0 + c3);
        float u4 = __ldg(xb0 + c4);
        float u5 = __ldg(xb0 + c5);
        float u6 = __ldg(xb0 + c6);
        float u7 = __ldg(xb0 + c7);
        float t0 = __ldg(xb1 + c0);
        float t1 = __ldg(xb1 + c1);
        float t2 = __ldg(xb1 + c2);
        float t3 = __ldg(xb1 + c3);
        float t4 = __ldg(xb1 + c4);
        float t5 = __ldg(xb1 + c5);
        float t6 = __ldg(xb1 + c6);
        float t7 = __ldg(xb1 + c7);
        if (gd != d_cur) {
            float inv = __ldg(&g_inv[d_cur]);
            unsigned oc = (unsigned)d_cur << 5;
            atomicAdd(o0 + oc, (p0 + p1) * inv);
            atomicAdd(o1 + oc, (q0 + q1) * inv);
            p0 = p1 = q0 = q1 = 0.f;
            d_cur = gd;
        }
        float w0 = __int_as_float(r0.y), w1 = __int_as_float(r0.w);
        float w2 = __int_as_float(r1.y), w3 = __int_as_float(r1.w);
        float w4 = __int_as_float(r2.y), w5 = __int_as_float(r2.w);
        float w6 = __int_as_float(r3.y), w7 = __int_as_float(r3.w);
        p0 += w0 * u0;  p1 += w1 * u1;
        p0 += w2 * u2;  p1 += w3 * u3;
        p0 += w4 * u4;  p1 += w5 * u5;
        p0 += w6 * u6;  p1 += w7 * u7;
        q0 += w0 * t0;  q1 += w1 * t1;
        q0 += w2 * t2;  q1 += w3 * t3;
        q0 += w4 * t4;  q1 += w5 * t5;
        q0 += w6 * t6;  q1 += w7 * t7;
    }
    {
        float inv = __ldg(&g_inv[d_cur]);
        unsigned oc = (unsigned)d_cur << 5;
        atomicAdd(o0 + oc, (p0 + p1) * inv);
        atomicAdd(o1 + oc, (q0 + q1) * inv);
    }
}

// ---------------------------------------------------------------------------
// kernel_launch
// ---------------------------------------------------------------------------
extern "C" void kernel_launch(void* const* d_in, const int* in_sizes, int n_in,
                              void* d_out, int out_size) {
    const float* x       = (const float*)d_in[0];
    const float* weights = (const float*)d_in[1];
    const int*   src_idx = (const int*)d_in[2];
    const int*   dst_idx = (const int*)d_in[3];
    float*       out     = (float*)d_out;
    const int n_edges = in_sizes[1];
    const int n_out4  = out_size / 4;

    void* hist_ptr = nullptr;
    cudaGetSymbolAddress(&hist_ptr, g_hist);
    cudaMemsetAsync(hist_ptr, 0, DST_SIZE * sizeof(unsigned long long), 0);

    k_hist<<<(n_edges + 255) / 256, 256>>>(weights, dst_idx, n_edges,
                                           (float4*)out, n_out4);
    k_scan<<<SCAN_BLOCKS, SCAN_CHUNK>>>();
    k_scatter<<<(n_edges + 255) / 256, 256>>>(weights, src_idx, dst_idx, n_edges);
    // 2 batch-pairs * WPB_REDUCE warps, 4 warps/block, pair-major, ONE launch.
    k_reduce<<<(2 * WPB_REDUCE) / 4, 128>>>(x, out);
}